// round 1
// baseline (speedup 1.0000x reference)
#include <cuda_runtime.h>
#include <cuda_bf16.h>

#define NPTS 16384
#define QBLK 128                 // threads per block = queries per block
#define NBLK (NPTS / QBLK)       // 128 blocks per direction
#define TILE 1024                // targets staged in smem per chunk (16 KB)

// Scratch (no allocations allowed): packed points {x, y, z, |p|^2}
__device__ float4 g_pack[2][NPTS];        // [0] = Xc, [1] = Xt
__device__ float  g_partial[2 * NBLK];    // per-block partial sums of clamped mins

// ---------------------------------------------------------------------------
// Pack each cloud as float4 {x, y, z, x^2+y^2+z^2}
// ---------------------------------------------------------------------------
__global__ void chamfer_prep_kernel(const float* __restrict__ xc,
                                    const float* __restrict__ xt) {
    int i = blockIdx.x * blockDim.x + threadIdx.x;
    if (i < NPTS) {
        float x = xc[3 * i + 0], y = xc[3 * i + 1], z = xc[3 * i + 2];
        g_pack[0][i] = make_float4(x, y, z, fmaf(x, x, fmaf(y, y, z * z)));
        x = xt[3 * i + 0]; y = xt[3 * i + 1]; z = xt[3 * i + 2];
        g_pack[1][i] = make_float4(x, y, z, fmaf(x, x, fmaf(y, y, z * z)));
    }
}

// ---------------------------------------------------------------------------
// Main kernel: one thread per query point, both directions in one grid.
// min_j ( |t_j|^2 - 2 q . t_j ), then  res = max(|q|^2 + min, 0)
// ---------------------------------------------------------------------------
__global__ __launch_bounds__(QBLK, 8) void chamfer_main_kernel() {
    __shared__ float4 st[TILE];
    __shared__ float  red[QBLK / 32];

    const int dir = (blockIdx.x >= NBLK) ? 1 : 0;
    const int bq  = blockIdx.x - dir * NBLK;

    const float4* __restrict__ qarr = g_pack[dir];
    const float4* __restrict__ tarr = g_pack[dir ^ 1];

    const float4 Q = qarr[bq * QBLK + threadIdx.x];
    const float a = -2.0f * Q.x;
    const float b = -2.0f * Q.y;
    const float c = -2.0f * Q.z;

    // 8 independent partial mins -> breaks the FMNMX RAW chain
    float m0 = 3.4e38f, m1 = 3.4e38f, m2 = 3.4e38f, m3 = 3.4e38f;
    float m4 = 3.4e38f, m5 = 3.4e38f, m6 = 3.4e38f, m7 = 3.4e38f;

    for (int base = 0; base < NPTS; base += TILE) {
        __syncthreads();   // protect smem reuse across chunks
        #pragma unroll
        for (int k = 0; k < TILE / QBLK; k++)
            st[threadIdx.x + k * QBLK] = tarr[base + threadIdx.x + k * QBLK];
        __syncthreads();

        #pragma unroll 2
        for (int j = 0; j < TILE; j += 8) {
            float4 p;
            float v;
            p = st[j + 0]; v = fmaf(a, p.x, fmaf(b, p.y, fmaf(c, p.z, p.w))); m0 = fminf(m0, v);
            p = st[j + 1]; v = fmaf(a, p.x, fmaf(b, p.y, fmaf(c, p.z, p.w))); m1 = fminf(m1, v);
            p = st[j + 2]; v = fmaf(a, p.x, fmaf(b, p.y, fmaf(c, p.z, p.w))); m2 = fminf(m2, v);
            p = st[j + 3]; v = fmaf(a, p.x, fmaf(b, p.y, fmaf(c, p.z, p.w))); m3 = fminf(m3, v);
            p = st[j + 4]; v = fmaf(a, p.x, fmaf(b, p.y, fmaf(c, p.z, p.w))); m4 = fminf(m4, v);
            p = st[j + 5]; v = fmaf(a, p.x, fmaf(b, p.y, fmaf(c, p.z, p.w))); m5 = fminf(m5, v);
            p = st[j + 6]; v = fmaf(a, p.x, fmaf(b, p.y, fmaf(c, p.z, p.w))); m6 = fminf(m6, v);
            p = st[j + 7]; v = fmaf(a, p.x, fmaf(b, p.y, fmaf(c, p.z, p.w))); m7 = fminf(m7, v);
        }
    }

    float m = fminf(fminf(fminf(m0, m1), fminf(m2, m3)),
                    fminf(fminf(m4, m5), fminf(m6, m7)));
    // clamp matches reference's maximum(d2, 0): min of clamped == clamp of min
    float res = fmaxf(Q.w + m, 0.0f);

    // block-wide deterministic sum
    #pragma unroll
    for (int off = 16; off > 0; off >>= 1)
        res += __shfl_xor_sync(0xFFFFFFFFu, res, off);

    int lane = threadIdx.x & 31;
    int warp = threadIdx.x >> 5;
    if (lane == 0) red[warp] = res;
    __syncthreads();
    if (threadIdx.x == 0) {
        float s = red[0];
        #pragma unroll
        for (int w = 1; w < QBLK / 32; w++) s += red[w];
        g_partial[blockIdx.x] = s;
    }
}

// ---------------------------------------------------------------------------
// Final reduction: sum all 256 partials, scale by 1/N (same N both directions)
// ---------------------------------------------------------------------------
__global__ void chamfer_finalize_kernel(float* __restrict__ out) {
    __shared__ float s[2 * NBLK];
    int tid = threadIdx.x;
    s[tid] = g_partial[tid];
    __syncthreads();
    #pragma unroll
    for (int off = NBLK; off > 0; off >>= 1) {
        if (tid < off) s[tid] += s[tid + off];
        __syncthreads();
    }
    if (tid == 0) out[0] = s[0] * (1.0f / (float)NPTS);
}

// ---------------------------------------------------------------------------
extern "C" void kernel_launch(void* const* d_in, const int* in_sizes, int n_in,
                              void* d_out, int out_size) {
    const float* xc = (const float*)d_in[0];
    const float* xt = (const float*)d_in[1];
    float* out = (float*)d_out;

    chamfer_prep_kernel<<<(NPTS + 255) / 256, 256>>>(xc, xt);
    chamfer_main_kernel<<<2 * NBLK, QBLK>>>();
    chamfer_finalize_kernel<<<1, 2 * NBLK>>>(out);
}

// round 2
// speedup vs baseline: 1.5588x; 1.5588x over previous
#include <cuda_runtime.h>
#include <cuda_bf16.h>
#include <cstdint>

#define NPTS   16384
#define THREADS 128
#define QPT    4                       // queries per thread (2 packed f32x2 pairs)
#define QPB    (THREADS * QPT)         // 512 queries per block
#define NQC    (NPTS / QPB)            // 32 query chunks per direction
#define THALVES 4                      // target-dimension split
#define TPB    (NPTS / THALVES)        // 4096 targets per block
#define TILE   1024                    // targets staged per smem chunk

// ---- device scratch (no allocations allowed) ----
__device__ float4 g_pack[2][NPTS];            // {x, y, z, |p|^2}
__device__ float4 g_dupA[2][NPTS];            // {x, x, y, y}  (f32x2 broadcast-ready)
__device__ float4 g_dupB[2][NPTS];            // {z, z, w, w}
__device__ float  g_minh[2][THALVES][NPTS];   // per-(dir, target-half, query) min
__device__ float  g_partial[128];

#define FMA2(d, a, b, c) \
    asm("fma.rn.f32x2 %0, %1, %2, %3;" : "=l"(d) : "l"(a), "l"(b), "l"(c))
#define PACK2(d, lo, hi) \
    asm("mov.b64 %0, {%1, %2};" : "=l"(d) : "f"(lo), "f"(hi))
#define UNPK2(lo, hi, s) \
    asm("mov.b64 {%0, %1}, %2;" : "=f"(lo), "=f"(hi) : "l"(s))

// ---------------------------------------------------------------------------
__global__ void chamfer_prep_kernel(const float* __restrict__ xc,
                                    const float* __restrict__ xt) {
    int i = blockIdx.x * blockDim.x + threadIdx.x;
    if (i >= NPTS) return;
    const float* src[2] = {xc, xt};
    #pragma unroll
    for (int s = 0; s < 2; s++) {
        float x = src[s][3 * i + 0], y = src[s][3 * i + 1], z = src[s][3 * i + 2];
        float w = fmaf(x, x, fmaf(y, y, z * z));
        g_pack[s][i] = make_float4(x, y, z, w);
        g_dupA[s][i] = make_float4(x, x, y, y);
        g_dupB[s][i] = make_float4(z, z, w, w);
    }
}

// ---------------------------------------------------------------------------
// grid = 2 dirs * THALVES * NQC = 256 blocks, 128 threads.
// Each thread owns 4 queries (2 packed pairs), scans 4096 targets.
// ---------------------------------------------------------------------------
__global__ __launch_bounds__(THREADS) void chamfer_main_kernel() {
    __shared__ ulonglong2 sA[TILE];   // {xx, yy} per target
    __shared__ ulonglong2 sB[TILE];   // {zz, ww} per target

    const int bid = blockIdx.x;
    const int dir = bid >> 7;             // 0..1
    const int rem = bid & 127;
    const int th  = rem >> 5;             // 0..3  target half
    const int qc  = rem & 31;             // 0..31 query chunk
    const int qbase = qc * QPB;
    const int tbase = th * TPB;
    const int tid = threadIdx.x;

    const float4* __restrict__ qarr = g_pack[dir];
    const int tgt = dir ^ 1;

    // 4 queries per thread
    float4 Q0 = qarr[qbase + tid];
    float4 Q1 = qarr[qbase + 128 + tid];
    float4 Q2 = qarr[qbase + 256 + tid];
    float4 Q3 = qarr[qbase + 384 + tid];

    unsigned long long aP, bP, cP, aQ, bQ, cQ;
    PACK2(aP, -2.0f * Q0.x, -2.0f * Q1.x);
    PACK2(bP, -2.0f * Q0.y, -2.0f * Q1.y);
    PACK2(cP, -2.0f * Q0.z, -2.0f * Q1.z);
    PACK2(aQ, -2.0f * Q2.x, -2.0f * Q3.x);
    PACK2(bQ, -2.0f * Q2.y, -2.0f * Q3.y);
    PACK2(cQ, -2.0f * Q2.z, -2.0f * Q3.z);

    // two accumulators per query (even/odd unroll lanes) to break FMNMX RAW
    float m0a = 3.4e38f, m0b = 3.4e38f, m1a = 3.4e38f, m1b = 3.4e38f;
    float m2a = 3.4e38f, m2b = 3.4e38f, m3a = 3.4e38f, m3b = 3.4e38f;

    for (int base = 0; base < TPB; base += TILE) {
        __syncthreads();
        #pragma unroll
        for (int k = 0; k < TILE / THREADS; k++) {
            int idx = tid + k * THREADS;
            int j = tbase + base + idx;
            *reinterpret_cast<float4*>(&sA[idx]) = g_dupA[tgt][j];
            *reinterpret_cast<float4*>(&sB[idx]) = g_dupB[tgt][j];
        }
        __syncthreads();

        #pragma unroll 2
        for (int j = 0; j < TILE; j += 2) {
            {
                ulonglong2 A = sA[j], B = sB[j];
                unsigned long long v, u;
                float vl, vh;
                FMA2(v, cP, B.x, B.y); FMA2(v, bP, A.y, v); FMA2(v, aP, A.x, v);
                UNPK2(vl, vh, v);
                m0a = fminf(m0a, vl); m1a = fminf(m1a, vh);
                FMA2(u, cQ, B.x, B.y); FMA2(u, bQ, A.y, u); FMA2(u, aQ, A.x, u);
                UNPK2(vl, vh, u);
                m2a = fminf(m2a, vl); m3a = fminf(m3a, vh);
            }
            {
                ulonglong2 A = sA[j + 1], B = sB[j + 1];
                unsigned long long v, u;
                float vl, vh;
                FMA2(v, cP, B.x, B.y); FMA2(v, bP, A.y, v); FMA2(v, aP, A.x, v);
                UNPK2(vl, vh, v);
                m0b = fminf(m0b, vl); m1b = fminf(m1b, vh);
                FMA2(u, cQ, B.x, B.y); FMA2(u, bQ, A.y, u); FMA2(u, aQ, A.x, u);
                UNPK2(vl, vh, u);
                m2b = fminf(m2b, vl); m3b = fminf(m3b, vh);
            }
        }
    }

    float* __restrict__ outm = g_minh[dir][th];
    outm[qbase + tid]       = fminf(m0a, m0b);
    outm[qbase + 128 + tid] = fminf(m1a, m1b);
    outm[qbase + 256 + tid] = fminf(m2a, m2b);
    outm[qbase + 384 + tid] = fminf(m3a, m3b);
}

// ---------------------------------------------------------------------------
// Combine the THALVES partial mins, clamp, and block-reduce.
// grid = 128 blocks * 256 threads = 32768 queries (both directions).
// ---------------------------------------------------------------------------
__global__ void chamfer_combine_kernel() {
    __shared__ float red[8];
    int idx = blockIdx.x * 256 + threadIdx.x;     // 0..32767
    int dir = idx >> 14;
    int q   = idx & (NPTS - 1);

    float m = fminf(fminf(g_minh[dir][0][q], g_minh[dir][1][q]),
                    fminf(g_minh[dir][2][q], g_minh[dir][3][q]));
    float r = fmaxf(g_pack[dir][q].w + m, 0.0f);

    #pragma unroll
    for (int off = 16; off > 0; off >>= 1)
        r += __shfl_xor_sync(0xFFFFFFFFu, r, off);

    int lane = threadIdx.x & 31, warp = threadIdx.x >> 5;
    if (lane == 0) red[warp] = r;
    __syncthreads();
    if (threadIdx.x == 0) {
        float s = red[0];
        #pragma unroll
        for (int w = 1; w < 8; w++) s += red[w];
        g_partial[blockIdx.x] = s;
    }
}

__global__ void chamfer_finalize_kernel(float* __restrict__ out) {
    __shared__ float s[128];
    int t = threadIdx.x;
    s[t] = g_partial[t];
    __syncthreads();
    #pragma unroll
    for (int off = 64; off > 0; off >>= 1) {
        if (t < off) s[t] += s[t + off];
        __syncthreads();
    }
    if (t == 0) out[0] = s[0] * (1.0f / (float)NPTS);
}

// ---------------------------------------------------------------------------
extern "C" void kernel_launch(void* const* d_in, const int* in_sizes, int n_in,
                              void* d_out, int out_size) {
    const float* xc = (const float*)d_in[0];
    const float* xt = (const float*)d_in[1];
    float* out = (float*)d_out;

    chamfer_prep_kernel<<<(NPTS + 255) / 256, 256>>>(xc, xt);
    chamfer_main_kernel<<<2 * THALVES * NQC, THREADS>>>();
    chamfer_combine_kernel<<<128, 256>>>();
    chamfer_finalize_kernel<<<1, 128>>>(out);
}

// round 6
// speedup vs baseline: 2.0174x; 1.2942x over previous
#include <cuda_runtime.h>
#include <cuda_bf16.h>
#include <cstdint>

#define NPTS    16384
#define THREADS 256
#define QPT     16                      // queries per thread (8 packed f32x2 pairs)
#define QPB     (THREADS * QPT)         // 4096 queries per block
#define NQC     (NPTS / QPB)            // 4 query chunks per direction
#define TSLICES 37                      // target slices: 2*4*37 = 296 = 2*148 blocks
#define TS_MAX  443                     // ceil(16384/37)

// ---- device scratch (no allocations allowed) ----
__device__ float4 g_pack[2][NPTS];            // {x, y, z, |p|^2}
__device__ float4 g_dupA[2][NPTS];            // {x, x, y, y}  (f32x2 broadcast-ready)
__device__ float4 g_dupB[2][NPTS];            // {z, z, w, w}
__device__ float  g_minh[2][TSLICES][NPTS];   // per-(dir, slice, query) min
__device__ float  g_partial[128];

#define FMA2(d, a, b, c) \
    asm("fma.rn.f32x2 %0, %1, %2, %3;" : "=l"(d) : "l"(a), "l"(b), "l"(c))
#define PACK2(d, lo, hi) \
    asm("mov.b64 %0, {%1, %2};" : "=l"(d) : "f"(lo), "f"(hi))
#define UNPK2(lo, hi, s) \
    asm("mov.b64 {%0, %1}, %2;" : "=f"(lo), "=f"(hi) : "l"(s))

// ---------------------------------------------------------------------------
__global__ void chamfer_prep_kernel(const float* __restrict__ xc,
                                    const float* __restrict__ xt) {
    int i = blockIdx.x * blockDim.x + threadIdx.x;
    if (i >= NPTS) return;
    const float* src[2] = {xc, xt};
    #pragma unroll
    for (int s = 0; s < 2; s++) {
        float x = src[s][3 * i + 0], y = src[s][3 * i + 1], z = src[s][3 * i + 2];
        float w = fmaf(x, x, fmaf(y, y, z * z));
        g_pack[s][i] = make_float4(x, y, z, w);
        g_dupA[s][i] = make_float4(x, x, y, y);
        g_dupB[s][i] = make_float4(z, z, w, w);
    }
}

// ---------------------------------------------------------------------------
// grid = 296 blocks (2 dirs x 4 qchunks x 37 tslices) = exactly 2 CTAs/SM,
// one wave, zero imbalance. 256 threads, 16 queries/thread, <=443 targets.
// ---------------------------------------------------------------------------
__global__ __launch_bounds__(THREADS, 2) void chamfer_main_kernel() {
    __shared__ ulonglong2 sA[TS_MAX];   // {xx, yy} per target
    __shared__ ulonglong2 sB[TS_MAX];   // {zz, ww} per target

    const int bid = blockIdx.x;
    const int dir = (bid >= 148) ? 1 : 0;
    const int rem = bid - dir * 148;
    const int qc  = rem / TSLICES;        // 0..3
    const int ts  = rem % TSLICES;        // 0..36
    const int qbase = qc * QPB;
    const int t0  = ts * TS_MAX;
    const int nt  = min(TS_MAX, NPTS - t0);
    const int tid = threadIdx.x;

    const float4* __restrict__ qarr = g_pack[dir];
    const int tgt = dir ^ 1;

    // stage this slice's targets (one shot; no re-staging loop)
    for (int idx = tid; idx < nt; idx += THREADS) {
        *reinterpret_cast<float4*>(&sA[idx]) = g_dupA[tgt][t0 + idx];
        *reinterpret_cast<float4*>(&sB[idx]) = g_dupB[tgt][t0 + idx];
    }

    // 16 queries per thread -> 8 packed coefficient triples
    unsigned long long aa[8], bb[8], cc[8];
    #pragma unroll
    for (int p = 0; p < 8; p++) {
        float4 Qe = qarr[qbase + (2 * p) * THREADS + tid];
        float4 Qo = qarr[qbase + (2 * p + 1) * THREADS + tid];
        PACK2(aa[p], -2.0f * Qe.x, -2.0f * Qo.x);
        PACK2(bb[p], -2.0f * Qe.y, -2.0f * Qo.y);
        PACK2(cc[p], -2.0f * Qe.z, -2.0f * Qo.z);
    }

    float mn[16];
    #pragma unroll
    for (int q = 0; q < 16; q++) mn[q] = 3.4e38f;

    __syncthreads();

    #pragma unroll 2
    for (int j = 0; j < nt; j++) {
        const ulonglong2 A = sA[j];     // {xx, yy}
        const ulonglong2 B = sB[j];     // {zz, ww}
        #pragma unroll
        for (int p = 0; p < 8; p++) {
            unsigned long long v;
            FMA2(v, cc[p], B.x, B.y);   // c*z + w
            FMA2(v, bb[p], A.y, v);     // + b*y
            FMA2(v, aa[p], A.x, v);     // + a*x
            float vl, vh;
            UNPK2(vl, vh, v);
            mn[2 * p]     = fminf(mn[2 * p], vl);
            mn[2 * p + 1] = fminf(mn[2 * p + 1], vh);
        }
    }

    float* __restrict__ outm = g_minh[dir][ts];
    #pragma unroll
    for (int q = 0; q < 16; q++)
        outm[qbase + q * THREADS + tid] = mn[q];
}

// ---------------------------------------------------------------------------
// Combine the TSLICES partial mins, clamp, and block-reduce.
// grid = 128 blocks * 256 threads = 32768 queries (both directions).
// ---------------------------------------------------------------------------
__global__ void chamfer_combine_kernel() {
    __shared__ float red[8];
    int idx = blockIdx.x * 256 + threadIdx.x;     // 0..32767
    int dir = idx >> 14;
    int q   = idx & (NPTS - 1);

    float m = 3.4e38f;
    #pragma unroll
    for (int s = 0; s < TSLICES; s++)
        m = fminf(m, g_minh[dir][s][q]);
    float r = fmaxf(g_pack[dir][q].w + m, 0.0f);

    #pragma unroll
    for (int off = 16; off > 0; off >>= 1)
        r += __shfl_xor_sync(0xFFFFFFFFu, r, off);

    int lane = threadIdx.x & 31, warp = threadIdx.x >> 5;
    if (lane == 0) red[warp] = r;
    __syncthreads();
    if (threadIdx.x == 0) {
        float s = red[0];
        #pragma unroll
        for (int w = 1; w < 8; w++) s += red[w];
        g_partial[blockIdx.x] = s;
    }
}

__global__ void chamfer_finalize_kernel(float* __restrict__ out) {
    __shared__ float s[128];
    int t = threadIdx.x;
    s[t] = g_partial[t];
    __syncthreads();
    #pragma unroll
    for (int off = 64; off > 0; off >>= 1) {
        if (t < off) s[t] += s[t + off];
        __syncthreads();
    }
    if (t == 0) out[0] = s[0] * (1.0f / (float)NPTS);
}

// ---------------------------------------------------------------------------
extern "C" void kernel_launch(void* const* d_in, const int* in_sizes, int n_in,
                              void* d_out, int out_size) {
    const float* xc = (const float*)d_in[0];
    const float* xt = (const float*)d_in[1];
    float* out = (float*)d_out;

    chamfer_prep_kernel<<<64, 256>>>(xc, xt);
    chamfer_main_kernel<<<296, THREADS>>>();
    chamfer_combine_kernel<<<128, 256>>>();
    chamfer_finalize_kernel<<<1, 128>>>(out);
}